// round 1
// baseline (speedup 1.0000x reference)
#include <cuda_runtime.h>

// KohonenMap: dist = ||x||^2 - 2 x.W^T + ||w||^2, bmu = argmin_k, out = W[bmu]
// N=65536, K=4096, D=512 (derived dynamically, D fixed at 512)

#define D_DIM 512
#define BM 128
#define BN 128
#define BK 32
#define TM 8
#define TN 8
#define NTHREADS 256

__device__ float g_w2[8192];

// --- Pass 0: per-neuron squared norms (one warp per row) ---
__global__ void w2_kernel(const float* __restrict__ w, int K) {
    int warp = (blockIdx.x * blockDim.x + threadIdx.x) >> 5;
    int lane = threadIdx.x & 31;
    if (warp >= K) return;
    const float4* row = reinterpret_cast<const float4*>(w + (size_t)warp * D_DIM);
    float s = 0.f;
#pragma unroll
    for (int i = 0; i < D_DIM / 4 / 32; ++i) {
        float4 v = row[lane + i * 32];
        s += v.x * v.x + v.y * v.y + v.z * v.z + v.w * v.w;
    }
#pragma unroll
    for (int off = 16; off > 0; off >>= 1)
        s += __shfl_xor_sync(0xffffffff, s, off);
    if (lane == 0) g_w2[warp] = s;
}

// --- Pass 1: fused GEMM + argmin + gather ---
// Block: 128 rows of x. Loops over all K neurons in chunks of 128.
// Each thread owns an 8x8 accumulator tile; running (best,idx) kept in registers.
__global__ __launch_bounds__(NTHREADS, 2)
void som_kernel(const float* __restrict__ x, const float* __restrict__ w,
                float* __restrict__ out, int N, int K) {
    // GEMM tiles and reduction buffers alias (reduction runs after all GEMM work)
    __shared__ union SMem {
        struct {
            float As[BK][BM];   // x tile, transposed  (16 KB)
            float Bs[BK][BN];   // w tile, transposed  (16 KB)
        } g;
        struct {
            float redv[BM][17];
            int   redi[BM][17];
        } r;
    } sm;
    __shared__ float w2s[BN];
    __shared__ int   bmu[BM];

    const int tid = threadIdx.x;
    const int tx = tid & 15;        // neuron-tile coordinate
    const int ty = tid >> 4;        // row-tile coordinate
    const int rowBase = blockIdx.x * BM;

    // global-load mapping: 32 rows x 8 float4-cols per pass
    const int lr  = tid >> 3;       // 0..31
    const int lc4 = tid & 7;        // 0..7

    float best[TM];
    int   bidx[TM];
#pragma unroll
    for (int i = 0; i < TM; i++) { best[i] = 3.4e38f; bidx[i] = 0; }

    for (int nc = 0; nc < K; nc += BN) {
        __syncthreads();            // protect w2s against previous epilogue readers
        if (tid < BN) w2s[tid] = g_w2[nc + tid];

        float acc[TM][TN];
#pragma unroll
        for (int i = 0; i < TM; i++)
#pragma unroll
            for (int j = 0; j < TN; j++) acc[i][j] = 0.f;

        for (int kc = 0; kc < D_DIM; kc += BK) {
            __syncthreads();        // previous inner-loop reads done
            // load x tile transposed: As[k][m]
#pragma unroll
            for (int r = 0; r < BM; r += 32) {
                float4 v = *reinterpret_cast<const float4*>(
                    x + (size_t)(rowBase + lr + r) * D_DIM + kc + lc4 * 4);
                sm.g.As[lc4 * 4 + 0][lr + r] = v.x;
                sm.g.As[lc4 * 4 + 1][lr + r] = v.y;
                sm.g.As[lc4 * 4 + 2][lr + r] = v.z;
                sm.g.As[lc4 * 4 + 3][lr + r] = v.w;
            }
            // load w tile transposed: Bs[k][n]
#pragma unroll
            for (int r = 0; r < BN; r += 32) {
                float4 v = *reinterpret_cast<const float4*>(
                    w + (size_t)(nc + lr + r) * D_DIM + kc + lc4 * 4);
                sm.g.Bs[lc4 * 4 + 0][lr + r] = v.x;
                sm.g.Bs[lc4 * 4 + 1][lr + r] = v.y;
                sm.g.Bs[lc4 * 4 + 2][lr + r] = v.z;
                sm.g.Bs[lc4 * 4 + 3][lr + r] = v.w;
            }
            __syncthreads();

#pragma unroll
            for (int k = 0; k < BK; ++k) {
                float a[TM], b[TN];
                *reinterpret_cast<float4*>(&a[0]) =
                    *reinterpret_cast<const float4*>(&sm.g.As[k][ty * TM]);
                *reinterpret_cast<float4*>(&a[4]) =
                    *reinterpret_cast<const float4*>(&sm.g.As[k][ty * TM + 4]);
                *reinterpret_cast<float4*>(&b[0]) =
                    *reinterpret_cast<const float4*>(&sm.g.Bs[k][tx * TN]);
                *reinterpret_cast<float4*>(&b[4]) =
                    *reinterpret_cast<const float4*>(&sm.g.Bs[k][tx * TN + 4]);
#pragma unroll
                for (int i = 0; i < TM; i++)
#pragma unroll
                    for (int j = 0; j < TN; j++)
                        acc[i][j] = fmaf(a[i], b[j], acc[i][j]);
            }
        }

        // epilogue: dist = w2 - 2*dot (x^2 term is argmin-invariant)
        // iterate j ascending -> strict < keeps earliest index (matches jnp.argmin)
#pragma unroll
        for (int j = 0; j < TN; j++) {
            float w2v = w2s[tx * TN + j];
            int idx = nc + tx * TN + j;
#pragma unroll
            for (int i = 0; i < TM; i++) {
                float dist = fmaf(-2.f, acc[i][j], w2v);
                if (dist < best[i]) { best[i] = dist; bidx[i] = idx; }
            }
        }
    }

    // cross-thread argmin reduction (16 threads share each row)
    __syncthreads();   // last inner-loop smem reads done before aliased writes
#pragma unroll
    for (int i = 0; i < TM; i++) {
        sm.r.redv[ty * TM + i][tx] = best[i];
        sm.r.redi[ty * TM + i][tx] = bidx[i];
    }
    __syncthreads();
    if (tid < BM) {
        float bv = sm.r.redv[tid][0];
        int   bi = sm.r.redi[tid][0];
#pragma unroll
        for (int t = 1; t < 16; t++) {
            float v = sm.r.redv[tid][t];
            int  ii = sm.r.redi[tid][t];
            if (v < bv || (v == bv && ii < bi)) { bv = v; bi = ii; }
        }
        bmu[tid] = bi;
    }
    __syncthreads();

    // gather winning weight rows (W is L2-resident: 8 MB)
    for (int t = tid; t < BM * (D_DIM / 4); t += NTHREADS) {
        int r = t >> 7;          // / (D_DIM/4)
        int c = t & 127;
        const float4* src = reinterpret_cast<const float4*>(
            w + (size_t)bmu[r] * D_DIM);
        reinterpret_cast<float4*>(out + (size_t)(rowBase + r) * D_DIM)[c] = src[c];
    }
}

extern "C" void kernel_launch(void* const* d_in, const int* in_sizes, int n_in,
                              void* d_out, int out_size) {
    const float* x = (const float*)d_in[0];
    const float* w = (const float*)d_in[1];
    float* out = (float*)d_out;
    int N = in_sizes[0] / D_DIM;
    int K = in_sizes[1] / D_DIM;

    // Pass 0: neuron norms (8 warps / block)
    w2_kernel<<<(K + 7) / 8, 256>>>(w, K);
    // Pass 1: fused GEMM + argmin + gather
    som_kernel<<<N / BM, NTHREADS>>>(x, w, out, N, K);
}

// round 6
// speedup vs baseline: 1.8902x; 1.8902x over previous
#include <cuda_runtime.h>
#include <cuda_fp16.h>
#include <cstdint>

// KohonenMap: 3xFP16-split mma.sync approx pass (top-2 per row) + exact fp32
// refine for small-margin rows (bitwise-identical FMA chain to the round-1
// kernel that matched the reference argmin on all rows).
#define NPTS 65536
#define KNEU 4096
#define DDIM 512
#define BM 128
#define BN 128
#define NTH 256
#define NST 4
#define NCHUNK (KNEU / BN)   // 32
#define NSTEP  (DDIM / 16)   // 32
#define TOTSTEP (NCHUNK * NSTEP)
#define MARGIN_TH 0.05f

__device__ __half g_xh[(size_t)NPTS * DDIM];
__device__ __half g_xl[(size_t)NPTS * DDIM];
__device__ __half g_wh[(size_t)KNEU * DDIM];
__device__ __half g_wl[(size_t)KNEU * DDIM];
__device__ float  g_w2[KNEU];

// smem: resident x-hi tile (128 x 512 fp16, 1040B rows) + 4 pipeline stages
#define A_STRIDE 1040
#define A_BYTES (BM * A_STRIDE)
#define BROW 48
#define STG_BH 0
#define STG_BL 6144
#define STG_AL 12288
#define STG_BYTES 18432
#define SMEM_DYN (A_BYTES + NST * STG_BYTES)   // 206848

extern __shared__ char dynsmem[];

__device__ __forceinline__ uint32_t smem_u32(const void* p) {
    uint32_t a;
    asm("{ .reg .u64 t; cvta.to.shared.u64 t, %1; cvt.u32.u64 %0, t; }" : "=r"(a) : "l"(p));
    return a;
}
__device__ __forceinline__ void cp16(uint32_t dst, const void* src) {
    asm volatile("cp.async.cg.shared.global [%0], [%1], 16;" :: "r"(dst), "l"(src));
}
#define CP_COMMIT() asm volatile("cp.async.commit_group;")
#define CP_WAIT2()  asm volatile("cp.async.wait_group 2;")

__device__ __forceinline__ void mma16816(float* c, const uint32_t* a, const uint32_t* b) {
    asm volatile(
        "mma.sync.aligned.m16n8k16.row.col.f32.f16.f16.f32 "
        "{%0,%1,%2,%3}, {%4,%5,%6,%7}, {%8,%9}, {%0,%1,%2,%3};"
        : "+f"(c[0]), "+f"(c[1]), "+f"(c[2]), "+f"(c[3])
        : "r"(a[0]), "r"(a[1]), "r"(a[2]), "r"(a[3]), "r"(b[0]), "r"(b[1]));
}

__device__ __forceinline__ void top2_upd(float d, int idx, float& v1, int& i1,
                                         float& v2, int& i2) {
    if (d < v1 || (d == v1 && idx < i1)) { v2 = v1; i2 = i1; v1 = d; i1 = idx; }
    else if (d < v2 || (d == v2 && idx < i2)) { v2 = d; i2 = idx; }
}

// ---------------- prep kernels ----------------
__global__ void prep16(const float* __restrict__ s, __half* __restrict__ dh,
                       __half* __restrict__ dl) {
    size_t i = (size_t)blockIdx.x * blockDim.x + threadIdx.x;
    float4 v = reinterpret_cast<const float4*>(s)[i];
    __half hx = __float2half_rn(v.x), hy = __float2half_rn(v.y);
    __half hz = __float2half_rn(v.z), hw = __float2half_rn(v.w);
    __half lx = __float2half_rn(v.x - __half2float(hx));
    __half ly = __float2half_rn(v.y - __half2float(hy));
    __half lz = __float2half_rn(v.z - __half2float(hz));
    __half lw = __float2half_rn(v.w - __half2float(hw));
    __half2 h01 = __halves2half2(hx, hy), h23 = __halves2half2(hz, hw);
    __half2 l01 = __halves2half2(lx, ly), l23 = __halves2half2(lz, lw);
    uint2 ph, pl;
    ph.x = *reinterpret_cast<uint32_t*>(&h01); ph.y = *reinterpret_cast<uint32_t*>(&h23);
    pl.x = *reinterpret_cast<uint32_t*>(&l01); pl.y = *reinterpret_cast<uint32_t*>(&l23);
    reinterpret_cast<uint2*>(dh)[i] = ph;
    reinterpret_cast<uint2*>(dl)[i] = pl;
}

__global__ void w2_kernel(const float* __restrict__ w) {
    int warp = (blockIdx.x * blockDim.x + threadIdx.x) >> 5;
    int lane = threadIdx.x & 31;
    if (warp >= KNEU) return;
    const float4* row = reinterpret_cast<const float4*>(w + (size_t)warp * DDIM);
    float s = 0.f;
#pragma unroll
    for (int i = 0; i < DDIM / 128; ++i) {
        float4 v = row[lane + i * 32];
        s += v.x * v.x + v.y * v.y + v.z * v.z + v.w * v.w;
    }
#pragma unroll
    for (int off = 16; off > 0; off >>= 1) s += __shfl_xor_sync(0xffffffff, s, off);
    if (lane == 0) g_w2[warp] = s;
}

// ---------------- main kernel ----------------
__global__ void __launch_bounds__(NTH, 1)
som_mma(const float* __restrict__ x, const float* __restrict__ w,
        float* __restrict__ out) {
    __shared__ float s_v1[BM][2], s_v2[BM][2];
    __shared__ int   s_i1[BM][2], s_i2[BM][2];
    __shared__ int   s_bmu[BM];

    const int tid = threadIdx.x;
    const int wid = tid >> 5;
    const int lane = tid & 31;
    const int g = lane >> 2;
    const int tig = lane & 3;
    const int warpM = wid & 3;
    const int warpN = wid >> 2;
    const int rowBase = blockIdx.x * BM;
    const uint32_t sb = smem_u32(dynsmem);

    const int ldRow = tid >> 1;
    const int ldHalf = tid & 1;

    // prologue: resident x-hi + first 3 stages
#pragma unroll
    for (int i = 0; i < 32; ++i) {
        int c = tid + i * NTH;
        int r = c >> 6, kc = c & 63;
        cp16(sb + r * A_STRIDE + kc * 16,
             &g_xh[(size_t)(rowBase + r) * DDIM + kc * 8]);
    }
#pragma unroll
    for (int p = 0; p < NST - 1; ++p) {
        int kk = (p & 31) * 16;
        uint32_t stg = sb + A_BYTES + (p & (NST - 1)) * STG_BYTES;
        uint32_t d = ldRow * BROW + ldHalf * 16;
        size_t so = (size_t)kk + ldHalf * 8;
        cp16(stg + STG_BH + d, &g_wh[(size_t)ldRow * DDIM + so]);
        cp16(stg + STG_BL + d, &g_wl[(size_t)ldRow * DDIM + so]);
        cp16(stg + STG_AL + d, &g_xl[(size_t)(rowBase + ldRow) * DDIM + so]);
        CP_COMMIT();
    }

    // running top-2 per owned sub-row
    float rv1[2][2], rv2[2][2];
    int   ri1[2][2], ri2[2][2];
#pragma unroll
    for (int a = 0; a < 2; ++a)
#pragma unroll
        for (int b = 0; b < 2; ++b) {
            rv1[a][b] = 3.4e38f; rv2[a][b] = 3.4e38f;
            ri1[a][b] = 0x7fffffff; ri2[a][b] = 0x7fffffff;
        }

    for (int ch = 0; ch < NCHUNK; ++ch) {
        float2 w2r[8];
#pragma unroll
        for (int nt = 0; nt < 8; ++nt)
            w2r[nt] = *reinterpret_cast<const float2*>(
                &g_w2[ch * BN + warpN * 64 + nt * 8 + tig * 2]);

        float acc[2][8][4];
#pragma unroll
        for (int mt = 0; mt < 2; ++mt)
#pragma unroll
            for (int nt = 0; nt < 8; ++nt)
#pragma unroll
                for (int i = 0; i < 4; ++i) acc[mt][nt][i] = 0.f;

        for (int s = 0; s < NSTEP; ++s) {
            const int gs = ch * NSTEP + s;
            CP_WAIT2();
            __syncthreads();

            const int gn = gs + NST - 1;
            if (gn < TOTSTEP) {
                int nc = (gn >> 5) * BN;
                int kk = (gn & 31) * 16;
                uint32_t stg = sb + A_BYTES + (gn & (NST - 1)) * STG_BYTES;
                uint32_t d = ldRow * BROW + ldHalf * 16;
                size_t so = (size_t)kk + ldHalf * 8;
                cp16(stg + STG_BH + d, &g_wh[(size_t)(nc + ldRow) * DDIM + so]);
                cp16(stg + STG_BL + d, &g_wl[(size_t)(nc + ldRow) * DDIM + so]);
                cp16(stg + STG_AL + d, &g_xl[(size_t)(rowBase + ldRow) * DDIM + so]);
            }
            CP_COMMIT();

            const char* stg = dynsmem + A_BYTES + (gs & (NST - 1)) * STG_BYTES;
            uint32_t ah[2][4], al[2][4], bh[8][2], bl[8][2];
#pragma unroll
            for (int mt = 0; mt < 2; ++mt) {
                int mrow = warpM * 32 + mt * 16 + g;
                const char* pa = dynsmem + mrow * A_STRIDE + s * 32 + tig * 4;
                ah[mt][0] = *(const uint32_t*)pa;
                ah[mt][1] = *(const uint32_t*)(pa + 8 * A_STRIDE);
                ah[mt][2] = *(const uint32_t*)(pa + 16);
                ah[mt][3] = *(const uint32_t*)(pa + 8 * A_STRIDE + 16);
                const char* pl = stg + STG_AL + mrow * BROW + tig * 4;
                al[mt][0] = *(const uint32_t*)pl;
                al[mt][1] = *(const uint32_t*)(pl + 8 * BROW);
                al[mt][2] = *(const uint32_t*)(pl + 16);
                al[mt][3] = *(const uint32_t*)(pl + 8 * BROW + 16);
            }
#pragma unroll
            for (int nt = 0; nt < 8; ++nt) {
                int n = warpN * 64 + nt * 8 + g;
                const char* pb = stg + STG_BH + n * BROW + tig * 4;
                bh[nt][0] = *(const uint32_t*)pb;
                bh[nt][1] = *(const uint32_t*)(pb + 16);
                const char* pc = stg + STG_BL + n * BROW + tig * 4;
                bl[nt][0] = *(const uint32_t*)pc;
                bl[nt][1] = *(const uint32_t*)(pc + 16);
            }
#pragma unroll
            for (int mt = 0; mt < 2; ++mt)
#pragma unroll
                for (int nt = 0; nt < 8; ++nt)
                    mma16816(acc[mt][nt], ah[mt], bh[nt]);   // hi*hi
#pragma unroll
            for (int mt = 0; mt < 2; ++mt)
#pragma unroll
                for (int nt = 0; nt < 8; ++nt)
                    mma16816(acc[mt][nt], ah[mt], bl[nt]);   // hi*lo
#pragma unroll
            for (int mt = 0; mt < 2; ++mt)
#pragma unroll
                for (int nt = 0; nt < 8; ++nt)
                    mma16816(acc[mt][nt], al[mt], bh[nt]);   // lo*hi
        }

        // epilogue: per-chunk local top-2, butterfly over 4 threads, merge into running
#pragma unroll
        for (int mt = 0; mt < 2; ++mt) {
#pragma unroll
            for (int r2 = 0; r2 < 2; ++r2) {
                float lv1 = 3.4e38f, lv2 = 3.4e38f;
                int li1 = 0x7fffffff, li2 = 0x7fffffff;
#pragma unroll
                for (int nt = 0; nt < 8; ++nt) {
#pragma unroll
                    for (int c2 = 0; c2 < 2; ++c2) {
                        float dot = acc[mt][nt][r2 * 2 + c2];
                        float w2v = c2 ? w2r[nt].y : w2r[nt].x;
                        float dist = fmaf(-2.f, dot, w2v);
                        int idx = ch * BN + warpN * 64 + nt * 8 + tig * 2 + c2;
                        top2_upd(dist, idx, lv1, li1, lv2, li2);
                    }
                }
#pragma unroll
                for (int off = 1; off < 4; off <<= 1) {
                    float o1 = __shfl_xor_sync(0xffffffffu, lv1, off);
                    int   p1 = __shfl_xor_sync(0xffffffffu, li1, off);
                    float o2 = __shfl_xor_sync(0xffffffffu, lv2, off);
                    int   p2 = __shfl_xor_sync(0xffffffffu, li2, off);
                    top2_upd(o1, p1, lv1, li1, lv2, li2);
                    top2_upd(o2, p2, lv1, li1, lv2, li2);
                }
                top2_upd(lv1, li1, rv1[mt][r2], ri1[mt][r2], rv2[mt][r2], ri2[mt][r2]);
                top2_upd(lv2, li2, rv1[mt][r2], ri1[mt][r2], rv2[mt][r2], ri2[mt][r2]);
            }
        }
    }

    // cross-warp merge + margin test + exact refine
    if (tig == 0) {
#pragma unroll
        for (int mt = 0; mt < 2; ++mt)
#pragma unroll
            for (int r2 = 0; r2 < 2; ++r2) {
                int row = warpM * 32 + mt * 16 + g + r2 * 8;
                s_v1[row][warpN] = rv1[mt][r2]; s_i1[row][warpN] = ri1[mt][r2];
                s_v2[row][warpN] = rv2[mt][r2]; s_i2[row][warpN] = ri2[mt][r2];
            }
    }
    __syncthreads();
    if (tid < BM) {
        float v1 = s_v1[tid][0], v2 = s_v2[tid][0];
        int   i1 = s_i1[tid][0], i2 = s_i2[tid][0];
        top2_upd(s_v1[tid][1], s_i1[tid][1], v1, i1, v2, i2);
        top2_upd(s_v2[tid][1], s_i2[tid][1], v1, i1, v2, i2);
        int bmu = i1;
        if (v2 - v1 < MARGIN_TH) {
            // exact fp32 refine: identical FMA chain to the validated round-1 kernel
            const float* xr = x + (size_t)(rowBase + tid) * DDIM;
            const float* w1p = w + (size_t)i1 * DDIM;
            const float* w2p = w + (size_t)i2 * DDIM;
            float a1 = 0.f, a2 = 0.f;
#pragma unroll 8
            for (int k = 0; k < DDIM; ++k) {
                float xv = xr[k];
                a1 = fmaf(xv, w1p[k], a1);
                a2 = fmaf(xv, w2p[k], a2);
            }
            float d1 = fmaf(-2.f, a1, g_w2[i1]);
            float d2 = fmaf(-2.f, a2, g_w2[i2]);
            if (d2 < d1 || (d2 == d1 && i2 < i1)) bmu = i2;
        }
        s_bmu[tid] = bmu;
    }
    __syncthreads();

    for (int t = tid; t < BM * (DDIM / 4); t += NTH) {
        int r = t >> 7;
        int cc = t & 127;
        reinterpret_cast<float4*>(out + (size_t)(rowBase + r) * DDIM)[cc] =
            reinterpret_cast<const float4*>(w + (size_t)s_bmu[r] * DDIM)[cc];
    }
}

// ---------------- launch ----------------
extern "C" void kernel_launch(void* const* d_in, const int* in_sizes, int n_in,
                              void* d_out, int out_size) {
    const float* x = (const float*)d_in[0];
    const float* w = (const float*)d_in[1];
    float* out = (float*)d_out;

    __half *xh, *xl, *wh, *wl;
    cudaGetSymbolAddress((void**)&xh, g_xh);
    cudaGetSymbolAddress((void**)&xl, g_xl);
    cudaGetSymbolAddress((void**)&wh, g_wh);
    cudaGetSymbolAddress((void**)&wl, g_wl);

    prep16<<<(NPTS * DDIM / 4) / 256, 256>>>(x, xh, xl);
    prep16<<<(KNEU * DDIM / 4) / 256, 256>>>(w, wh, wl);
    w2_kernel<<<KNEU / 8, 256>>>(w);

    cudaFuncSetAttribute(som_mma, cudaFuncAttributeMaxDynamicSharedMemorySize, SMEM_DYN);
    som_mma<<<NPTS / BM, NTH, SMEM_DYN>>>(x, w, out);
}

// round 7
// speedup vs baseline: 2.5304x; 1.3387x over previous
#include <cuda_runtime.h>
#include <cuda_fp16.h>
#include <cstdint>

// KohonenMap: 3xFP16-split mma.sync (hh+hl+lh) top-2 pass + exact fp32 refine.
// R7: 512 threads (16 warps, 4/SMSP) + ldmatrix fragment loads.
#define NPTS 65536
#define KNEU 4096
#define DDIM 512
#define BM 128
#define BN 128
#define NTH 512
#define NST 4
#define NCHUNK (KNEU / BN)   // 32
#define NSTEP  (DDIM / 16)   // 32
#define TOTSTEP (NCHUNK * NSTEP)
#define MARGIN_TH 0.05f

__device__ __half g_xh[(size_t)NPTS * DDIM];
__device__ __half g_xl[(size_t)NPTS * DDIM];
__device__ __half g_wh[(size_t)KNEU * DDIM];
__device__ __half g_wl[(size_t)KNEU * DDIM];
__device__ float  g_w2[KNEU];

// smem: resident x-hi tile (128 x 512 fp16, 1040B rows) + 4 pipeline stages
#define A_STRIDE 1040
#define A_BYTES (BM * A_STRIDE)
#define BROW 48
#define STG_BH 0
#define STG_BL 6144
#define STG_AL 12288
#define STG_BYTES 18432
#define SMEM_DYN (A_BYTES + NST * STG_BYTES)   // 206848

extern __shared__ char dynsmem[];

__device__ __forceinline__ uint32_t smem_u32(const void* p) {
    uint32_t a;
    asm("{ .reg .u64 t; cvta.to.shared.u64 t, %1; cvt.u32.u64 %0, t; }" : "=r"(a) : "l"(p));
    return a;
}
__device__ __forceinline__ void cp16(uint32_t dst, const void* src) {
    asm volatile("cp.async.cg.shared.global [%0], [%1], 16;" :: "r"(dst), "l"(src));
}
#define CP_COMMIT() asm volatile("cp.async.commit_group;")
#define CP_WAIT2()  asm volatile("cp.async.wait_group 2;")

__device__ __forceinline__ void ldm_x4(uint32_t* r, uint32_t addr) {
    asm volatile("ldmatrix.sync.aligned.m8n8.x4.shared.b16 {%0,%1,%2,%3}, [%4];"
        : "=r"(r[0]), "=r"(r[1]), "=r"(r[2]), "=r"(r[3]) : "r"(addr));
}

__device__ __forceinline__ void mma16816(float* c, const uint32_t* a, const uint32_t* b) {
    asm volatile(
        "mma.sync.aligned.m16n8k16.row.col.f32.f16.f16.f32 "
        "{%0,%1,%2,%3}, {%4,%5,%6,%7}, {%8,%9}, {%0,%1,%2,%3};"
        : "+f"(c[0]), "+f"(c[1]), "+f"(c[2]), "+f"(c[3])
        : "r"(a[0]), "r"(a[1]), "r"(a[2]), "r"(a[3]), "r"(b[0]), "r"(b[1]));
}

__device__ __forceinline__ void top2_upd(float d, int idx, float& v1, int& i1,
                                         float& v2, int& i2) {
    if (d < v1 || (d == v1 && idx < i1)) { v2 = v1; i2 = i1; v1 = d; i1 = idx; }
    else if (d < v2 || (d == v2 && idx < i2)) { v2 = d; i2 = idx; }
}

// ---------------- prep kernels ----------------
__global__ void prep16(const float* __restrict__ s, __half* __restrict__ dh,
                       __half* __restrict__ dl) {
    size_t i = (size_t)blockIdx.x * blockDim.x + threadIdx.x;
    float4 v = reinterpret_cast<const float4*>(s)[i];
    __half hx = __float2half_rn(v.x), hy = __float2half_rn(v.y);
    __half hz = __float2half_rn(v.z), hw = __float2half_rn(v.w);
    __half lx = __float2half_rn(v.x - __half2float(hx));
    __half ly = __float2half_rn(v.y - __half2float(hy));
    __half lz = __float2half_rn(v.z - __half2float(hz));
    __half lw = __float2half_rn(v.w - __half2float(hw));
    __half2 h01 = __halves2half2(hx, hy), h23 = __halves2half2(hz, hw);
    __half2 l01 = __halves2half2(lx, ly), l23 = __halves2half2(lz, lw);
    uint2 ph, pl;
    ph.x = *reinterpret_cast<uint32_t*>(&h01); ph.y = *reinterpret_cast<uint32_t*>(&h23);
    pl.x = *reinterpret_cast<uint32_t*>(&l01); pl.y = *reinterpret_cast<uint32_t*>(&l23);
    reinterpret_cast<uint2*>(dh)[i] = ph;
    reinterpret_cast<uint2*>(dl)[i] = pl;
}

__global__ void w2_kernel(const float* __restrict__ w) {
    int warp = (blockIdx.x * blockDim.x + threadIdx.x) >> 5;
    int lane = threadIdx.x & 31;
    if (warp >= KNEU) return;
    const float4* row = reinterpret_cast<const float4*>(w + (size_t)warp * DDIM);
    float s = 0.f;
#pragma unroll
    for (int i = 0; i < DDIM / 128; ++i) {
        float4 v = row[lane + i * 32];
        s += v.x * v.x + v.y * v.y + v.z * v.z + v.w * v.w;
    }
#pragma unroll
    for (int off = 16; off > 0; off >>= 1) s += __shfl_xor_sync(0xffffffff, s, off);
    if (lane == 0) g_w2[warp] = s;
}

// ---------------- main kernel ----------------
__global__ void __launch_bounds__(NTH, 1)
som_mma(const float* __restrict__ x, const float* __restrict__ w,
        float* __restrict__ out) {
    __shared__ float s_v1[BM][4], s_v2[BM][4];
    __shared__ int   s_i1[BM][4], s_i2[BM][4];
    __shared__ int   s_bmu[BM];

    const int tid = threadIdx.x;
    const int wid = tid >> 5;
    const int lane = tid & 31;
    const int g = lane >> 2;
    const int tig = lane & 3;
    const int warpM = wid & 3;        // 4 M-warps, 32 rows each
    const int warpN = wid >> 2;       // 4 N-warps, 32 cols each
    const int rowBase = blockIdx.x * BM;
    const uint32_t sb = smem_u32(dynsmem);

    // ldmatrix lane decomposition
    const int lr = lane & 15;         // A row within m16 tile-pair
    const int lh = lane >> 4;         // A k-half
    const int bt = lane >> 3;         // B tile index 0..3
    const int br = lane & 7;          // B row within tile
    const int b_noff = ((bt >> 1) << 3) + br;   // n offset 0..15
    const int b_koff = (bt & 1) << 4;           // 0 or 16 bytes

    // stage-fill mapping (threads 0-255 fill, all commit)
    const int ldRow = (tid & 255) >> 1;
    const int ldHalf = tid & 1;

    // prologue: resident x-hi + first 3 stages
#pragma unroll
    for (int i = 0; i < 16; ++i) {
        int c = tid + i * NTH;
        int r = c >> 6, kc = c & 63;
        cp16(sb + r * A_STRIDE + kc * 16,
             &g_xh[(size_t)(rowBase + r) * DDIM + kc * 8]);
    }
#pragma unroll
    for (int p = 0; p < NST - 1; ++p) {
        if (tid < 256) {
            int kk = (p & 31) * 16;
            uint32_t stg = sb + A_BYTES + (p & (NST - 1)) * STG_BYTES;
            uint32_t d = ldRow * BROW + ldHalf * 16;
            size_t so = (size_t)kk + ldHalf * 8;
            cp16(stg + STG_BH + d, &g_wh[(size_t)ldRow * DDIM + so]);
            cp16(stg + STG_BL + d, &g_wl[(size_t)ldRow * DDIM + so]);
            cp16(stg + STG_AL + d, &g_xl[(size_t)(rowBase + ldRow) * DDIM + so]);
        }
        CP_COMMIT();
    }

    // running top-2 per owned sub-row
    float rv1[2][2], rv2[2][2];
    int   ri1[2][2], ri2[2][2];
#pragma unroll
    for (int a = 0; a < 2; ++a)
#pragma unroll
        for (int b = 0; b < 2; ++b) {
            rv1[a][b] = 3.4e38f; rv2[a][b] = 3.4e38f;
            ri1[a][b] = 0x7fffffff; ri2[a][b] = 0x7fffffff;
        }

    for (int ch = 0; ch < NCHUNK; ++ch) {
        float2 w2r[4];
#pragma unroll
        for (int nt = 0; nt < 4; ++nt)
            w2r[nt] = *reinterpret_cast<const float2*>(
                &g_w2[ch * BN + warpN * 32 + nt * 8 + tig * 2]);

        float acc[2][4][4];
#pragma unroll
        for (int mt = 0; mt < 2; ++mt)
#pragma unroll
            for (int nt = 0; nt < 4; ++nt)
#pragma unroll
                for (int i = 0; i < 4; ++i) acc[mt][nt][i] = 0.f;

        for (int s = 0; s < NSTEP; ++s) {
            const int gs = ch * NSTEP + s;
            CP_WAIT2();
            __syncthreads();

            const int gn = gs + NST - 1;
            if (gn < TOTSTEP && tid < 256) {
                int nc = (gn >> 5) * BN;
                int kk = (gn & 31) * 16;
                uint32_t stg = sb + A_BYTES + (gn & (NST - 1)) * STG_BYTES;
                uint32_t d = ldRow * BROW + ldHalf * 16;
                size_t so = (size_t)kk + ldHalf * 8;
                cp16(stg + STG_BH + d, &g_wh[(size_t)(nc + ldRow) * DDIM + so]);
                cp16(stg + STG_BL + d, &g_wl[(size_t)(nc + ldRow) * DDIM + so]);
                cp16(stg + STG_AL + d, &g_xl[(size_t)(rowBase + ldRow) * DDIM + so]);
            }
            CP_COMMIT();

            // ---- fragment loads via ldmatrix ----
            const uint32_t stg32 = sb + A_BYTES + (gs & (NST - 1)) * STG_BYTES;
            uint32_t ah[2][4], al[2][4], bh[4][2], bl[4][2];

            uint32_t aaddr = sb + (warpM * 32 + lr) * A_STRIDE + s * 32 + lh * 16;
            ldm_x4(ah[0], aaddr);
            ldm_x4(ah[1], aaddr + 16 * A_STRIDE);
            uint32_t aladdr = stg32 + STG_AL + (warpM * 32 + lr) * BROW + lh * 16;
            ldm_x4(al[0], aladdr);
            ldm_x4(al[1], aladdr + 16 * BROW);
            uint32_t bhaddr = stg32 + STG_BH + (warpN * 32 + b_noff) * BROW + b_koff;
            ldm_x4(&bh[0][0], bhaddr);
            ldm_x4(&bh[2][0], bhaddr + 16 * BROW);
            uint32_t bladdr = stg32 + STG_BL + (warpN * 32 + b_noff) * BROW + b_koff;
            ldm_x4(&bl[0][0], bladdr);
            ldm_x4(&bl[2][0], bladdr + 16 * BROW);

#pragma unroll
            for (int mt = 0; mt < 2; ++mt)
#pragma unroll
                for (int nt = 0; nt < 4; ++nt)
                    mma16816(acc[mt][nt], ah[mt], bh[nt]);   // hi*hi
#pragma unroll
            for (int mt = 0; mt < 2; ++mt)
#pragma unroll
                for (int nt = 0; nt < 4; ++nt)
                    mma16816(acc[mt][nt], ah[mt], bl[nt]);   // hi*lo
#pragma unroll
            for (int mt = 0; mt < 2; ++mt)
#pragma unroll
                for (int nt = 0; nt < 4; ++nt)
                    mma16816(acc[mt][nt], al[mt], bh[nt]);   // lo*hi
        }

        // epilogue: per-chunk local top-2, butterfly over 4 threads, merge
#pragma unroll
        for (int mt = 0; mt < 2; ++mt) {
#pragma unroll
            for (int r2 = 0; r2 < 2; ++r2) {
                float lv1 = 3.4e38f, lv2 = 3.4e38f;
                int li1 = 0x7fffffff, li2 = 0x7fffffff;
#pragma unroll
                for (int nt = 0; nt < 4; ++nt) {
#pragma unroll
                    for (int c2 = 0; c2 < 2; ++c2) {
                        float dot = acc[mt][nt][r2 * 2 + c2];
                        float w2v = c2 ? w2r[nt].y : w2r[nt].x;
                        float dist = fmaf(-2.f, dot, w2v);
                        int idx = ch * BN + warpN * 32 + nt * 8 + tig * 2 + c2;
                        top2_upd(dist, idx, lv1, li1, lv2, li2);
                    }
                }
#pragma unroll
                for (int off = 1; off < 4; off <<= 1) {
                    float o1 = __shfl_xor_sync(0xffffffffu, lv1, off);
                    int   p1 = __shfl_xor_sync(0xffffffffu, li1, off);
                    float o2 = __shfl_xor_sync(0xffffffffu, lv2, off);
                    int   p2 = __shfl_xor_sync(0xffffffffu, li2, off);
                    top2_upd(o1, p1, lv1, li1, lv2, li2);
                    top2_upd(o2, p2, lv1, li1, lv2, li2);
                }
                top2_upd(lv1, li1, rv1[mt][r2], ri1[mt][r2], rv2[mt][r2], ri2[mt][r2]);
                top2_upd(lv2, li2, rv1[mt][r2], ri1[mt][r2], rv2[mt][r2], ri2[mt][r2]);
            }
        }
    }

    // cross-warp merge + margin test + exact refine
    if (tig == 0) {
#pragma unroll
        for (int mt = 0; mt < 2; ++mt)
#pragma unroll
            for (int r2 = 0; r2 < 2; ++r2) {
                int row = warpM * 32 + mt * 16 + g + r2 * 8;
                s_v1[row][warpN] = rv1[mt][r2]; s_i1[row][warpN] = ri1[mt][r2];
                s_v2[row][warpN] = rv2[mt][r2]; s_i2[row][warpN] = ri2[mt][r2];
            }
    }
    __syncthreads();
    if (tid < BM) {
        float v1 = s_v1[tid][0], v2 = s_v2[tid][0];
        int   i1 = s_i1[tid][0], i2 = s_i2[tid][0];
#pragma unroll
        for (int wn = 1; wn < 4; ++wn) {
            top2_upd(s_v1[tid][wn], s_i1[tid][wn], v1, i1, v2, i2);
            top2_upd(s_v2[tid][wn], s_i2[tid][wn], v1, i1, v2, i2);
        }
        int bmu = i1;
        if (v2 - v1 < MARGIN_TH) {
            // exact fp32 refine: identical FMA chain to the validated r1 kernel
            const float* xr = x + (size_t)(rowBase + tid) * DDIM;
            const float* w1p = w + (size_t)i1 * DDIM;
            const float* w2p = w + (size_t)i2 * DDIM;
            float a1 = 0.f, a2 = 0.f;
#pragma unroll 8
            for (int k = 0; k < DDIM; ++k) {
                float xv = xr[k];
                a1 = fmaf(xv, w1p[k], a1);
                a2 = fmaf(xv, w2p[k], a2);
            }
            float d1 = fmaf(-2.f, a1, g_w2[i1]);
            float d2 = fmaf(-2.f, a2, g_w2[i2]);
            if (d2 < d1 || (d2 == d1 && i2 < i1)) bmu = i2;
        }
        s_bmu[tid] = bmu;
    }
    __syncthreads();

    for (int t = tid; t < BM * (DDIM / 4); t += NTH) {
        int r = t >> 7;
        int cc = t & 127;
        reinterpret_cast<float4*>(out + (size_t)(rowBase + r) * DDIM)[cc] =
            reinterpret_cast<const float4*>(w + (size_t)s_bmu[r] * DDIM)[cc];
    }
}

// ---------------- launch ----------------
extern "C" void kernel_launch(void* const* d_in, const int* in_sizes, int n_in,
                              void* d_out, int out_size) {
    const float* x = (const float*)d_in[0];
    const float* w = (const float*)d_in[1];
    float* out = (float*)d_out;

    __half *xh, *xl, *wh, *wl;
    cudaGetSymbolAddress((void**)&xh, g_xh);
    cudaGetSymbolAddress((void**)&xl, g_xl);
    cudaGetSymbolAddress((void**)&wh, g_wh);
    cudaGetSymbolAddress((void**)&wl, g_wl);

    prep16<<<(NPTS * DDIM / 4) / 256, 256>>>(x, xh, xl);
    prep16<<<(KNEU * DDIM / 4) / 256, 256>>>(w, wh, wl);
    w2_kernel<<<KNEU / 8, 256>>>(w);

    cudaFuncSetAttribute(som_mma, cudaFuncAttributeMaxDynamicSharedMemorySize, SMEM_DYN);
    som_mma<<<NPTS / BM, NTH, SMEM_DYN>>>(x, w, out);
}

// round 9
// speedup vs baseline: 2.7020x; 1.0678x over previous
#include <cuda_runtime.h>
#include <cuda_fp16.h>
#include <cstdint>

// KohonenMap: 3xFP16-split mma.sync (hh+hl+lh) top-2 pass + exact fp32 refine.
// R9: R8 mbarrier pipeline with the .noinc fix (default cp.async.mbarrier.arrive
// increments the pending count -> barrier never flips -> R8 hang).
#define NPTS 65536
#define KNEU 4096
#define DDIM 512
#define BM 128
#define BN 128
#define NTH 512
#define NST 4
#define NCHUNK (KNEU / BN)   // 32
#define NSTEP  (DDIM / 16)   // 32
#define TOTSTEP (NCHUNK * NSTEP)
#define MARGIN_TH 0.05f

__device__ __half g_xh[(size_t)NPTS * DDIM];
__device__ __half g_xl[(size_t)NPTS * DDIM];
__device__ __half g_wh[(size_t)KNEU * DDIM];
__device__ __half g_wl[(size_t)KNEU * DDIM];
__device__ float  g_w2[KNEU];

// smem: resident x-hi tile (128 x 512 fp16, 1040B rows) + 4 pipeline stages
#define A_STRIDE 1040
#define A_BYTES (BM * A_STRIDE)
#define BROW 48
#define STG_BH 0
#define STG_BL 6144
#define STG_AL 12288
#define STG_BYTES 18432
#define SMEM_DYN (A_BYTES + NST * STG_BYTES)   // 206848

extern __shared__ char dynsmem[];

__device__ __forceinline__ uint32_t smem_u32(const void* p) {
    uint32_t a;
    asm("{ .reg .u64 t; cvta.to.shared.u64 t, %1; cvt.u32.u64 %0, t; }" : "=r"(a) : "l"(p));
    return a;
}
__device__ __forceinline__ void cp16(uint32_t dst, const void* src) {
    asm volatile("cp.async.cg.shared.global [%0], [%1], 16;" :: "r"(dst), "l"(src));
}
#define CP_COMMIT() asm volatile("cp.async.commit_group;")
#define CP_WAIT0()  asm volatile("cp.async.wait_group 0;")

#define MBAR_INIT(mb, c) \
    asm volatile("mbarrier.init.shared.b64 [%0], %1;" :: "r"(mb), "r"(c) : "memory")
#define MBAR_ARRIVE(mb) \
    asm volatile("mbarrier.arrive.shared.b64 _, [%0];" :: "r"(mb) : "memory")
// .noinc: this arrival counts against the initialized expected count.
#define CPASYNC_MBAR_ARRIVE(mb) \
    asm volatile("cp.async.mbarrier.arrive.noinc.shared.b64 [%0];" :: "r"(mb) : "memory")

#define MBAR_WAIT_PARITY(mbar_addr, par) do {                                            \
    uint32_t _mb = (uint32_t)(mbar_addr); uint32_t _p = (uint32_t)(par); uint32_t _done; \
    asm volatile("{ .reg .pred p; mbarrier.try_wait.parity.acquire.cta.shared::cta.b64 " \
                 "p, [%1], %2; selp.b32 %0,1,0,p; }"                                     \
                 : "=r"(_done) : "r"(_mb), "r"(_p) : "memory");                          \
    if (!_done) {                                                                        \
        asm volatile("{ .reg .pred P1; WL_%=: "                                          \
            "mbarrier.try_wait.parity.acquire.cta.shared::cta.b64 P1, [%0], %1, 0x989680;"\
            " @P1 bra.uni WD_%=; bra.uni WL_%=; WD_%=: }"                                \
            :: "r"(_mb), "r"(_p) : "memory");                                            \
    }                                                                                    \
} while (0)

__device__ __forceinline__ void ldm_x4(uint32_t* r, uint32_t addr) {
    asm volatile("ldmatrix.sync.aligned.m8n8.x4.shared.b16 {%0,%1,%2,%3}, [%4];"
        : "=r"(r[0]), "=r"(r[1]), "=r"(r[2]), "=r"(r[3]) : "r"(addr));
}

__device__ __forceinline__ void mma16816(float* c, const uint32_t* a, const uint32_t* b) {
    asm volatile(
        "mma.sync.aligned.m16n8k16.row.col.f32.f16.f16.f32 "
        "{%0,%1,%2,%3}, {%4,%5,%6,%7}, {%8,%9}, {%0,%1,%2,%3};"
        : "+f"(c[0]), "+f"(c[1]), "+f"(c[2]), "+f"(c[3])
        : "r"(a[0]), "r"(a[1]), "r"(a[2]), "r"(a[3]), "r"(b[0]), "r"(b[1]));
}

__device__ __forceinline__ void top2_upd(float d, int idx, float& v1, int& i1,
                                         float& v2, int& i2) {
    if (d < v1 || (d == v1 && idx < i1)) { v2 = v1; i2 = i1; v1 = d; i1 = idx; }
    else if (d < v2 || (d == v2 && idx < i2)) { v2 = d; i2 = idx; }
}

// ---------------- prep kernels ----------------
__global__ void prep16(const float* __restrict__ s, __half* __restrict__ dh,
                       __half* __restrict__ dl) {
    size_t i = (size_t)blockIdx.x * blockDim.x + threadIdx.x;
    float4 v = reinterpret_cast<const float4*>(s)[i];
    __half hx = __float2half_rn(v.x), hy = __float2half_rn(v.y);
    __half hz = __float2half_rn(v.z), hw = __float2half_rn(v.w);
    __half lx = __float2half_rn(v.x - __half2float(hx));
    __half ly = __float2half_rn(v.y - __half2float(hy));
    __half lz = __float2half_rn(v.z - __half2float(hz));
    __half lw = __float2half_rn(v.w - __half2float(hw));
    __half2 h01 = __halves2half2(hx, hy), h23 = __halves2half2(hz, hw);
    __half2 l01 = __halves2half2(lx, ly), l23 = __halves2half2(lz, lw);
    uint2 ph, pl;
    ph.x = *reinterpret_cast<uint32_t*>(&h01); ph.y = *reinterpret_cast<uint32_t*>(&h23);
    pl.x = *reinterpret_cast<uint32_t*>(&l01); pl.y = *reinterpret_cast<uint32_t*>(&l23);
    reinterpret_cast<uint2*>(dh)[i] = ph;
    reinterpret_cast<uint2*>(dl)[i] = pl;
}

__global__ void w2_kernel(const float* __restrict__ w) {
    int warp = (blockIdx.x * blockDim.x + threadIdx.x) >> 5;
    int lane = threadIdx.x & 31;
    if (warp >= KNEU) return;
    const float4* row = reinterpret_cast<const float4*>(w + (size_t)warp * DDIM);
    float s = 0.f;
#pragma unroll
    for (int i = 0; i < DDIM / 128; ++i) {
        float4 v = row[lane + i * 32];
        s += v.x * v.x + v.y * v.y + v.z * v.z + v.w * v.w;
    }
#pragma unroll
    for (int off = 16; off > 0; off >>= 1) s += __shfl_xor_sync(0xffffffff, s, off);
    if (lane == 0) g_w2[warp] = s;
}

// ---------------- main kernel ----------------
__global__ void __launch_bounds__(NTH, 1)
som_mma(const float* __restrict__ x, const float* __restrict__ w,
        float* __restrict__ out) {
    __shared__ __align__(8) uint64_t mbar[2 * NST];   // full[0..3], empty[4..7]
    __shared__ float s_v1[BM][4], s_v2[BM][4];
    __shared__ int   s_i1[BM][4], s_i2[BM][4];
    __shared__ int   s_bmu[BM];

    const int tid = threadIdx.x;
    const int wid = tid >> 5;
    const int lane = tid & 31;
    const int g4 = lane >> 2;
    const int tig = lane & 3;
    const int warpM = wid & 3;        // 4 M-warps, 32 rows each
    const int warpN = wid >> 2;       // 4 N-warps, 32 cols each
    const int rowBase = blockIdx.x * BM;
    const uint32_t sb = smem_u32(dynsmem);
    const uint32_t mb = smem_u32(mbar);

    // ldmatrix lane decomposition
    const int lr = lane & 15;
    const int lh = lane >> 4;
    const int bt = lane >> 3;
    const int br = lane & 7;
    const int b_noff = ((bt >> 1) << 3) + br;
    const int b_koff = (bt & 1) << 4;

    // stage-fill mapping (threads 0-255 fill)
    const int ldRow = (tid & 255) >> 1;
    const int ldHalf = tid & 1;

    if (tid == 0) {
#pragma unroll
        for (int s = 0; s < NST; ++s) {
            MBAR_INIT(mb + s * 8, 256);             // full: 256 cp-arrivals
            MBAR_INIT(mb + (NST + s) * 8, 16);      // empty: 16 warp-arrivals
        }
    }
    __syncthreads();   // barriers visible before any arrival

    // prologue: resident x-hi (grouped) ...
#pragma unroll
    for (int i = 0; i < 16; ++i) {
        int c = tid + i * NTH;
        int r = c >> 6, kc = c & 63;
        cp16(sb + r * A_STRIDE + kc * 16,
             &g_xh[(size_t)(rowBase + r) * DDIM + kc * 8]);
    }
    CP_COMMIT();
    // ... then first NST-1 stage fills (mbarrier-tracked; stages fresh -> no empty wait)
#pragma unroll
    for (int p = 0; p < NST - 1; ++p) {
        if (tid < 256) {
            int kk = (p & 31) * 16;
            uint32_t stg = sb + A_BYTES + p * STG_BYTES;
            uint32_t d = ldRow * BROW + ldHalf * 16;
            size_t so = (size_t)kk + ldHalf * 8;
            cp16(stg + STG_BH + d, &g_wh[(size_t)ldRow * DDIM + so]);
            cp16(stg + STG_BL + d, &g_wl[(size_t)ldRow * DDIM + so]);
            cp16(stg + STG_AL + d, &g_xl[(size_t)(rowBase + ldRow) * DDIM + so]);
            CPASYNC_MBAR_ARRIVE(mb + p * 8);
        }
    }
    CP_WAIT0();        // resident-A group complete
    __syncthreads();   // A visible to all warps

    // running top-2 per owned sub-row
    float rv1[2][2], rv2[2][2];
    int   ri1[2][2], ri2[2][2];
#pragma unroll
    for (int a = 0; a < 2; ++a)
#pragma unroll
        for (int b = 0; b < 2; ++b) {
            rv1[a][b] = 3.4e38f; rv2[a][b] = 3.4e38f;
            ri1[a][b] = 0x7fffffff; ri2[a][b] = 0x7fffffff;
        }

    for (int ch = 0; ch < NCHUNK; ++ch) {
        float2 w2r[4];
#pragma unroll
        for (int nt = 0; nt < 4; ++nt)
            w2r[nt] = *reinterpret_cast<const float2*>(
                &g_w2[ch * BN + warpN * 32 + nt * 8 + tig * 2]);

        float acc[2][4][4];
#pragma unroll
        for (int mt = 0; mt < 2; ++mt)
#pragma unroll
            for (int nt = 0; nt < 4; ++nt)
#pragma unroll
                for (int i = 0; i < 4; ++i) acc[mt][nt][i] = 0.f;

        for (int s = 0; s < NSTEP; ++s) {
            const int gs = ch * NSTEP + s;
            const int st = gs & (NST - 1);

            // ---- consumer: wait stage full (stateless parity) ----
            MBAR_WAIT_PARITY(mb + st * 8, (gs >> 2) & 1);

            const uint32_t stg32 = sb + A_BYTES + st * STG_BYTES;
            uint32_t ah[2][4], al[2][4], bh[4][2], bl[4][2];

            uint32_t aaddr = sb + (warpM * 32 + lr) * A_STRIDE + s * 32 + lh * 16;
            ldm_x4(ah[0], aaddr);
            ldm_x4(ah[1], aaddr + 16 * A_STRIDE);
            uint32_t aladdr = stg32 + STG_AL + (warpM * 32 + lr) * BROW + lh * 16;
            ldm_x4(al[0], aladdr);
            ldm_x4(al[1], aladdr + 16 * BROW);
            uint32_t bhaddr = stg32 + STG_BH + (warpN * 32 + b_noff) * BROW + b_koff;
            ldm_x4(&bh[0][0], bhaddr);
            ldm_x4(&bh[2][0], bhaddr + 16 * BROW);
            uint32_t bladdr = stg32 + STG_BL + (warpN * 32 + b_noff) * BROW + b_koff;
            ldm_x4(&bl[0][0], bladdr);
            ldm_x4(&bl[2][0], bladdr + 16 * BROW);

#pragma unroll
            for (int mt = 0; mt < 2; ++mt)
#pragma unroll
                for (int nt = 0; nt < 4; ++nt)
                    mma16816(acc[mt][nt], ah[mt], bh[nt]);   // hi*hi
#pragma unroll
            for (int mt = 0; mt < 2; ++mt)
#pragma unroll
                for (int nt = 0; nt < 4; ++nt)
                    mma16816(acc[mt][nt], ah[mt], bl[nt]);   // hi*lo
#pragma unroll
            for (int mt = 0; mt < 2; ++mt)
#pragma unroll
                for (int nt = 0; nt < 4; ++nt)
                    mma16816(acc[mt][nt], al[mt], bh[nt]);   // lo*hi

            // MMA issue implies our LDSMs completed -> this warp is done with the stage
            if (lane == 0) MBAR_ARRIVE(mb + (NST + st) * 8);

            // ---- producer: refill stage gs+NST-1 ----
            const int gn = gs + NST - 1;
            if (gn < TOTSTEP && tid < 256) {
                const int stn = gn & (NST - 1);
                if (gn >= NST)   // pass >= 1: wait consumers of previous pass
                    MBAR_WAIT_PARITY(mb + (NST + stn) * 8, ((gn >> 2) + 1) & 1);
                int nc = (gn >> 5) * BN;
                int kk = (gn & 31) * 16;
                uint32_t stg = sb + A_BYTES + stn * STG_BYTES;
                uint32_t d = ldRow * BROW + ldHalf * 16;
                size_t so = (size_t)kk + ldHalf * 8;
                cp16(stg + STG_BH + d, &g_wh[(size_t)(nc + ldRow) * DDIM + so]);
                cp16(stg + STG_BL + d, &g_wl[(size_t)(nc + ldRow) * DDIM + so]);
                cp16(stg + STG_AL + d, &g_xl[(size_t)(rowBase + ldRow) * DDIM + so]);
                CPASYNC_MBAR_ARRIVE(mb + stn * 8);
            }
        }

        // epilogue: per-chunk local top-2, butterfly over 4 threads, merge
#pragma unroll
        for (int mt = 0; mt < 2; ++mt) {
#pragma unroll
            for (int r2 = 0; r2 < 2; ++r2) {
                float lv1 = 3.4e38f, lv2 = 3.4e38f;
                int li1 = 0x7fffffff, li2 = 0x7fffffff;
#pragma unroll
                for (int nt = 0; nt < 4; ++nt) {
#pragma unroll
                    for (int c2 = 0; c2 < 2; ++c2) {
                        float dot = acc[mt][nt][r2 * 2 + c2];
                        float w2v = c2 ? w2r[nt].y : w2r[nt].x;
                        float dist = fmaf(-2.f, dot, w2v);
                        int idx = ch * BN + warpN * 32 + nt * 8 + tig * 2 + c2;
                        top2_upd(dist, idx, lv1, li1, lv2, li2);
                    }
                }
#pragma unroll
                for (int off = 1; off < 4; off <<= 1) {
                    float o1 = __shfl_xor_sync(0xffffffffu, lv1, off);
                    int   p1 = __shfl_xor_sync(0xffffffffu, li1, off);
                    float o2 = __shfl_xor_sync(0xffffffffu, lv2, off);
                    int   p2 = __shfl_xor_sync(0xffffffffu, li2, off);
                    top2_upd(o1, p1, lv1, li1, lv2, li2);
                    top2_upd(o2, p2, lv1, li1, lv2, li2);
                }
                top2_upd(lv1, li1, rv1[mt][r2], ri1[mt][r2], rv2[mt][r2], ri2[mt][r2]);
                top2_upd(lv2, li2, rv1[mt][r2], ri1[mt][r2], rv2[mt][r2], ri2[mt][r2]);
            }
        }
    }

    // cross-warp merge + margin test + exact refine
    if (tig == 0) {
#pragma unroll
        for (int mt = 0; mt < 2; ++mt)
#pragma unroll
            for (int r2 = 0; r2 < 2; ++r2) {
                int row = warpM * 32 + mt * 16 + g4 + r2 * 8;
                s_v1[row][warpN] = rv1[mt][r2]; s_i1[row][warpN] = ri1[mt][r2];
                s_v2[row][warpN] = rv2[mt][r2]; s_i2[row][warpN] = ri2[mt][r2];
            }
    }
    __syncthreads();
    if (tid < BM) {
        float v1 = s_v1[tid][0], v2 = s_v2[tid][0];
        int   i1 = s_i1[tid][0], i2 = s_i2[tid][0];
#pragma unroll
        for (int wn = 1; wn < 4; ++wn) {
            top2_upd(s_v1[tid][wn], s_i1[tid][wn], v1, i1, v2, i2);
            top2_upd(s_v2[tid][wn], s_i2[tid][wn], v1, i1, v2, i2);
        }
        int bmu = i1;
        if (v2 - v1 < MARGIN_TH) {
            // exact fp32 refine: identical FMA chain to the validated r1 kernel
            const float* xr = x + (size_t)(rowBase + tid) * DDIM;
            const float* w1p = w + (size_t)i1 * DDIM;
            const float* w2p = w + (size_t)i2 * DDIM;
            float a1 = 0.f, a2 = 0.f;
#pragma unroll 8
            for (int k = 0; k < DDIM; ++k) {
                float xv = xr[k];
                a1 = fmaf(xv, w1p[k], a1);
                a2 = fmaf(xv, w2p[k], a2);
            }
            float d1 = fmaf(-2.f, a1, g_w2[i1]);
            float d2 = fmaf(-2.f, a2, g_w2[i2]);
            if (d2 < d1 || (d2 == d1 && i2 < i1)) bmu = i2;
        }
        s_bmu[tid] = bmu;
    }
    __syncthreads();

    for (int t = tid; t < BM * (DDIM / 4); t += NTH) {
        int r = t >> 7;
        int cc = t & 127;
        reinterpret_cast<float4*>(out + (size_t)(rowBase + r) * DDIM)[cc] =
            reinterpret_cast<const float4*>(w + (size_t)s_bmu[r] * DDIM)[cc];
    }
}

// ---------------- launch ----------------
extern "C" void kernel_launch(void* const* d_in, const int* in_sizes, int n_in,
                              void* d_out, int out_size) {
    const float* x = (const float*)d_in[0];
    const float* w = (const float*)d_in[1];
    float* out = (float*)d_out;

    __half *xh, *xl, *wh, *wl;
    cudaGetSymbolAddress((void**)&xh, g_xh);
    cudaGetSymbolAddress((void**)&xl, g_xl);
    cudaGetSymbolAddress((void**)&wh, g_wh);
    cudaGetSymbolAddress((void**)&wl, g_wl);

    prep16<<<(NPTS * DDIM / 4) / 256, 256>>>(x, xh, xl);
    prep16<<<(KNEU * DDIM / 4) / 256, 256>>>(w, wh, wl);
    w2_kernel<<<KNEU / 8, 256>>>(w);

    cudaFuncSetAttribute(som_mma, cudaFuncAttributeMaxDynamicSharedMemorySize, SMEM_DYN);
    som_mma<<<NPTS / BM, NTH, SMEM_DYN>>>(x, w, out);
}

// round 10
// speedup vs baseline: 2.9132x; 1.0782x over previous
#include <cuda_runtime.h>
#include <cuda_fp16.h>
#include <cstdint>

// KohonenMap: 3xFP16-split mma.sync (hh+hl+lh) top-2 pass + exact fp32 refine.
// R10: 2 CTAs/SM (BM=64, 256 thr, <=128 regs) — two independent pipelines per SM
// to break the skew-1 producer/consumer coupling; A streamed (L2-resident).
#define NPTS 65536
#define KNEU 4096
#define DDIM 512
#define BM 64
#define BN 128
#define NTH 256
#define NST 4
#define NCHUNK (KNEU / BN)   // 32
#define NSTEP  (DDIM / 16)   // 32
#define TOTSTEP (NCHUNK * NSTEP)
#define MARGIN_TH 0.05f

__device__ __half g_xh[(size_t)NPTS * DDIM];
__device__ __half g_xl[(size_t)NPTS * DDIM];
__device__ __half g_wh[(size_t)KNEU * DDIM];
__device__ __half g_wl[(size_t)KNEU * DDIM];
__device__ float  g_w2[KNEU];

// stage: Ah[64x48B] Al[64x48B] Bh[128x48B] Bl[128x48B] = 18432 B
#define BROW 48
#define STG_AH 0
#define STG_AL 3072
#define STG_BH 6144
#define STG_BL 12288
#define STG_BYTES 18432
#define SMEM_DYN (NST * STG_BYTES)   // 73728 -> 2 CTAs/SM

extern __shared__ char dynsmem[];

__device__ __forceinline__ uint32_t smem_u32(const void* p) {
    uint32_t a;
    asm("{ .reg .u64 t; cvta.to.shared.u64 t, %1; cvt.u32.u64 %0, t; }" : "=r"(a) : "l"(p));
    return a;
}
__device__ __forceinline__ void cp16(uint32_t dst, const void* src) {
    asm volatile("cp.async.cg.shared.global [%0], [%1], 16;" :: "r"(dst), "l"(src));
}

#define MBAR_INIT(mb, c) \
    asm volatile("mbarrier.init.shared.b64 [%0], %1;" :: "r"(mb), "r"(c) : "memory")
#define MBAR_ARRIVE(mb) \
    asm volatile("mbarrier.arrive.shared.b64 _, [%0];" :: "r"(mb) : "memory")
#define CPASYNC_MBAR_ARRIVE(mb) \
    asm volatile("cp.async.mbarrier.arrive.noinc.shared.b64 [%0];" :: "r"(mb) : "memory")

#define MBAR_WAIT_PARITY(mbar_addr, par) do {                                            \
    uint32_t _mb = (uint32_t)(mbar_addr); uint32_t _p = (uint32_t)(par); uint32_t _done; \
    asm volatile("{ .reg .pred p; mbarrier.try_wait.parity.acquire.cta.shared::cta.b64 " \
                 "p, [%1], %2; selp.b32 %0,1,0,p; }"                                     \
                 : "=r"(_done) : "r"(_mb), "r"(_p) : "memory");                          \
    if (!_done) {                                                                        \
        asm volatile("{ .reg .pred P1; WL_%=: "                                          \
            "mbarrier.try_wait.parity.acquire.cta.shared::cta.b64 P1, [%0], %1, 0x989680;"\
            " @P1 bra.uni WD_%=; bra.uni WL_%=; WD_%=: }"                                \
            :: "r"(_mb), "r"(_p) : "memory");                                            \
    }                                                                                    \
} while (0)

__device__ __forceinline__ void ldm_x4(uint32_t* r, uint32_t addr) {
    asm volatile("ldmatrix.sync.aligned.m8n8.x4.shared.b16 {%0,%1,%2,%3}, [%4];"
        : "=r"(r[0]), "=r"(r[1]), "=r"(r[2]), "=r"(r[3]) : "r"(addr));
}

__device__ __forceinline__ void mma16816(float* c, const uint32_t* a, const uint32_t* b) {
    asm volatile(
        "mma.sync.aligned.m16n8k16.row.col.f32.f16.f16.f32 "
        "{%0,%1,%2,%3}, {%4,%5,%6,%7}, {%8,%9}, {%0,%1,%2,%3};"
        : "+f"(c[0]), "+f"(c[1]), "+f"(c[2]), "+f"(c[3])
        : "r"(a[0]), "r"(a[1]), "r"(a[2]), "r"(a[3]), "r"(b[0]), "r"(b[1]));
}

__device__ __forceinline__ void top2_upd(float d, int idx, float& v1, int& i1,
                                         float& v2, int& i2) {
    if (d < v1 || (d == v1 && idx < i1)) { v2 = v1; i2 = i1; v1 = d; i1 = idx; }
    else if (d < v2 || (d == v2 && idx < i2)) { v2 = d; i2 = idx; }
}

// ---------------- prep kernels ----------------
__global__ void prep16(const float* __restrict__ s, __half* __restrict__ dh,
                       __half* __restrict__ dl) {
    size_t i = (size_t)blockIdx.x * blockDim.x + threadIdx.x;
    float4 v = reinterpret_cast<const float4*>(s)[i];
    __half hx = __float2half_rn(v.x), hy = __float2half_rn(v.y);
    __half hz = __float2half_rn(v.z), hw = __float2half_rn(v.w);
    __half lx = __float2half_rn(v.x - __half2float(hx));
    __half ly = __float2half_rn(v.y - __half2float(hy));
    __half lz = __float2half_rn(v.z - __half2float(hz));
    __half lw = __float2half_rn(v.w - __half2float(hw));
    __half2 h01 = __halves2half2(hx, hy), h23 = __halves2half2(hz, hw);
    __half2 l01 = __halves2half2(lx, ly), l23 = __halves2half2(lz, lw);
    uint2 ph, pl;
    ph.x = *reinterpret_cast<uint32_t*>(&h01); ph.y = *reinterpret_cast<uint32_t*>(&h23);
    pl.x = *reinterpret_cast<uint32_t*>(&l01); pl.y = *reinterpret_cast<uint32_t*>(&l23);
    reinterpret_cast<uint2*>(dh)[i] = ph;
    reinterpret_cast<uint2*>(dl)[i] = pl;
}

__global__ void w2_kernel(const float* __restrict__ w) {
    int warp = (blockIdx.x * blockDim.x + threadIdx.x) >> 5;
    int lane = threadIdx.x & 31;
    if (warp >= KNEU) return;
    const float4* row = reinterpret_cast<const float4*>(w + (size_t)warp * DDIM);
    float s = 0.f;
#pragma unroll
    for (int i = 0; i < DDIM / 128; ++i) {
        float4 v = row[lane + i * 32];
        s += v.x * v.x + v.y * v.y + v.z * v.z + v.w * v.w;
    }
#pragma unroll
    for (int off = 16; off > 0; off >>= 1) s += __shfl_xor_sync(0xffffffff, s, off);
    if (lane == 0) g_w2[warp] = s;
}

// ---------------- main kernel ----------------
__global__ void __launch_bounds__(NTH, 2)
som_mma(const float* __restrict__ x, const float* __restrict__ w,
        float* __restrict__ out) {
    __shared__ __align__(8) uint64_t mbar[2 * NST];   // full[0..3], empty[4..7]
    __shared__ float s_v1[BM][4], s_v2[BM][4];
    __shared__ int   s_i1[BM][4], s_i2[BM][4];
    __shared__ int   s_bmu[BM];

    const int tid = threadIdx.x;
    const int wid = tid >> 5;
    const int lane = tid & 31;
    const int g4 = lane >> 2;
    const int tig = lane & 3;
    const int warpM = wid & 1;        // 2 M-warps, 32 rows each
    const int warpN = wid >> 1;       // 4 N-warps, 32 cols each
    const int rowBase = blockIdx.x * BM;
    const uint32_t sb = smem_u32(dynsmem);
    const uint32_t mb = smem_u32(mbar);

    // ldmatrix lane decomposition
    const int lr = lane & 15;
    const int lh = lane >> 4;
    const int bt = lane >> 3;
    const int br = lane & 7;
    const int b_noff = ((bt >> 1) << 3) + br;
    const int b_koff = (bt & 1) << 4;

    // fill mapping: B: (tid>>1, tid&1); A: buf=tid>>7, row=(tid&127)>>1, half=tid&1
    const int bRow = tid >> 1;
    const int hHalf = tid & 1;
    const int aRow = (tid & 127) >> 1;
    const uint32_t aBufOff = (uint32_t)(tid >> 7) * 3072;   // 0->Ah, 1->Al
    const __half* aSrcBase = (tid >= 128) ? g_xl : g_xh;

    if (tid == 0) {
#pragma unroll
        for (int s = 0; s < NST; ++s) {
            MBAR_INIT(mb + s * 8, NTH);             // full: 256 cp-arrivals
            MBAR_INIT(mb + (NST + s) * 8, 8);       // empty: 8 warp-arrivals
        }
    }
    __syncthreads();   // barriers visible before any arrival

    // prologue: first NST-1 stage fills (stages fresh -> no empty wait)
#pragma unroll
    for (int p = 0; p < NST - 1; ++p) {
        int kk = (p & 31) * 16;
        uint32_t stg = sb + p * STG_BYTES;
        uint32_t bd = bRow * BROW + hHalf * 16;
        size_t bso = (size_t)kk + hHalf * 8;
        cp16(stg + STG_BH + bd, &g_wh[(size_t)bRow * DDIM + bso]);
        cp16(stg + STG_BL + bd, &g_wl[(size_t)bRow * DDIM + bso]);
        cp16(stg + STG_AH + aBufOff + aRow * BROW + hHalf * 16,
             &aSrcBase[(size_t)(rowBase + aRow) * DDIM + bso]);
        CPASYNC_MBAR_ARRIVE(mb + p * 8);
    }

    // running top-2 per owned sub-row
    float rv1[2][2], rv2[2][2];
    int   ri1[2][2], ri2[2][2];
#pragma unroll
    for (int a = 0; a < 2; ++a)
#pragma unroll
        for (int b = 0; b < 2; ++b) {
            rv1[a][b] = 3.4e38f; rv2[a][b] = 3.4e38f;
            ri1[a][b] = 0x7fffffff; ri2[a][b] = 0x7fffffff;
        }

    for (int ch = 0; ch < NCHUNK; ++ch) {
        float2 w2r[4];
#pragma unroll
        for (int nt = 0; nt < 4; ++nt)
            w2r[nt] = *reinterpret_cast<const float2*>(
                &g_w2[ch * BN + warpN * 32 + nt * 8 + tig * 2]);

        float acc[2][4][4];
#pragma unroll
        for (int mt = 0; mt < 2; ++mt)
#pragma unroll
            for (int nt = 0; nt < 4; ++nt)
#pragma unroll
                for (int i = 0; i < 4; ++i) acc[mt][nt][i] = 0.f;

        for (int s = 0; s < NSTEP; ++s) {
            const int gs = ch * NSTEP + s;
            const int st = gs & (NST - 1);

            // ---- consumer: wait stage full (stateless parity) ----
            MBAR_WAIT_PARITY(mb + st * 8, (gs >> 2) & 1);

            const uint32_t stg32 = sb + st * STG_BYTES;
            uint32_t ah[2][4], al[2][4], bh[4][2], bl[4][2];

            uint32_t aaddr = stg32 + STG_AH + (warpM * 32 + lr) * BROW + lh * 16;
            ldm_x4(ah[0], aaddr);
            ldm_x4(ah[1], aaddr + 16 * BROW);
            uint32_t aladdr = stg32 + STG_AL + (warpM * 32 + lr) * BROW + lh * 16;
            ldm_x4(al[0], aladdr);
            ldm_x4(al[1], aladdr + 16 * BROW);
            uint32_t bhaddr = stg32 + STG_BH + (warpN * 32 + b_noff) * BROW + b_koff;
            ldm_x4(&bh[0][0], bhaddr);
            ldm_x4(&bh[2][0], bhaddr + 16 * BROW);
            uint32_t bladdr = stg32 + STG_BL + (warpN * 32 + b_noff) * BROW + b_koff;
            ldm_x4(&bl[0][0], bladdr);
            ldm_x4(&bl[2][0], bladdr + 16 * BROW);

#pragma unroll
            for (int mt = 0; mt < 2; ++mt)
#pragma unroll
                for (int nt = 0; nt < 4; ++nt)
                    mma16816(acc[mt][nt], ah[mt], bh[nt]);   // hi*hi
#pragma unroll
            for (int mt = 0; mt < 2; ++mt)
#pragma unroll
                for (int nt = 0; nt < 4; ++nt)
                    mma16816(acc[mt][nt], ah[mt], bl[nt]);   // hi*lo
#pragma unroll
            for (int mt = 0; mt < 2; ++mt)
#pragma unroll
                for (int nt = 0; nt < 4; ++nt)
                    mma16816(acc[mt][nt], al[mt], bh[nt]);   // lo*hi

            // MMA issue implies our LDSMs completed -> warp done with this stage
            if (lane == 0) MBAR_ARRIVE(mb + (NST + st) * 8);

            // ---- producer: refill stage gs+NST-1 ----
            const int gn = gs + NST - 1;
            if (gn < TOTSTEP) {
                const int stn = gn & (NST - 1);
                if (gn >= NST)   // pass >= 1: wait consumers of previous pass
                    MBAR_WAIT_PARITY(mb + (NST + stn) * 8, ((gn >> 2) + 1) & 1);
                int nc = (gn >> 5) * BN;
                int kk = (gn & 31) * 16;
                uint32_t stg = sb + stn * STG_BYTES;
                uint32_t bd = bRow * BROW + hHalf * 16;
                size_t bso = (size_t)kk + hHalf * 8;
                cp16(stg + STG_BH + bd, &g_wh[(size_t)(nc + bRow) * DDIM + bso]);
                cp16(stg + STG_BL + bd, &g_wl[(size_t)(nc + bRow) * DDIM + bso]);
                cp16(stg + STG_AH + aBufOff + aRow * BROW + hHalf * 16,
                     &aSrcBase[(size_t)(rowBase + aRow) * DDIM + bso]);
                CPASYNC_MBAR_ARRIVE(mb + stn * 8);
            }
        }

        // epilogue: per-chunk local top-2, butterfly over 4 threads, merge
#pragma unroll
        for (int mt = 0; mt < 2; ++mt) {
#pragma unroll
            for (int r2 = 0; r2 < 2; ++r2) {
                float lv1 = 3.4e38f, lv2 = 3.4e38f;
                int li1 = 0x7fffffff, li2 = 0x7fffffff;
#pragma unroll
                for (int nt = 0; nt < 4; ++nt) {
#pragma unroll
                    for (int c2 = 0; c2 < 2; ++c2) {
                        float dot = acc[mt][nt][r2 * 2 + c2];
                        float w2v = c2 ? w2r[nt].y : w2r[nt].x;
                        float dist = fmaf(-2.f, dot, w2v);
                        int idx = ch * BN + warpN * 32 + nt * 8 + tig * 2 + c2;
                        top2_upd(dist, idx, lv1, li1, lv2, li2);
                    }
                }
#pragma unroll
                for (int off = 1; off < 4; off <<= 1) {
                    float o1 = __shfl_xor_sync(0xffffffffu, lv1, off);
                    int   p1 = __shfl_xor_sync(0xffffffffu, li1, off);
                    float o2 = __shfl_xor_sync(0xffffffffu, lv2, off);
                    int   p2 = __shfl_xor_sync(0xffffffffu, li2, off);
                    top2_upd(o1, p1, lv1, li1, lv2, li2);
                    top2_upd(o2, p2, lv1, li1, lv2, li2);
                }
                top2_upd(lv1, li1, rv1[mt][r2], ri1[mt][r2], rv2[mt][r2], ri2[mt][r2]);
                top2_upd(lv2, li2, rv1[mt][r2], ri1[mt][r2], rv2[mt][r2], ri2[mt][r2]);
            }
        }
    }

    // cross-warp merge + margin test + exact refine
    if (tig == 0) {
#pragma unroll
        for (int mt = 0; mt < 2; ++mt)
#pragma unroll
            for (int r2 = 0; r2 < 2; ++r2) {
                int row = warpM * 32 + mt * 16 + g4 + r2 * 8;
                s_v1[row][warpN] = rv1[mt][r2]; s_i1[row][warpN] = ri1[mt][r2];
                s_v2[row][warpN] = rv2[mt][r2]; s_i2[row][warpN] = ri2[mt][r2];
            }
    }
    __syncthreads();
    if (tid < BM) {
        float v1 = s_v1[tid][0], v2 = s_v2[tid][0];
        int   i1 = s_i1[tid][0], i2 = s_i2[tid][0];
#pragma unroll
        for (int wn = 1; wn < 4; ++wn) {
            top2_upd(s_v1[tid][wn], s_i1[tid][wn], v1, i1, v2, i2);
            top2_upd(s_v2[tid][wn], s_i2[tid][wn], v1, i1, v2, i2);
        }
        int bmu = i1;
        if (v2 - v1 < MARGIN_TH) {
            // exact fp32 refine: identical FMA chain to the validated r1 kernel
            const float* xr = x + (size_t)(rowBase + tid) * DDIM;
            const float* w1p = w + (size_t)i1 * DDIM;
            const float* w2p = w + (size_t)i2 * DDIM;
            float a1 = 0.f, a2 = 0.f;
#pragma unroll 8
            for (int k = 0; k < DDIM; ++k) {
                float xv = xr[k];
                a1 = fmaf(xv, w1p[k], a1);
                a2 = fmaf(xv, w2p[k], a2);
            }
            float d1 = fmaf(-2.f, a1, g_w2[i1]);
            float d2 = fmaf(-2.f, a2, g_w2[i2]);
            if (d2 < d1 || (d2 == d1 && i2 < i1)) bmu = i2;
        }
        s_bmu[tid] = bmu;
    }
    __syncthreads();

    for (int t = tid; t < BM * (DDIM / 4); t += NTH) {
        int r = t >> 7;
        int cc = t & 127;
        reinterpret_cast<float4*>(out + (size_t)(rowBase + r) * DDIM)[cc] =
            reinterpret_cast<const float4*>(w + (size_t)s_bmu[r] * DDIM)[cc];
    }
}

// ---------------- launch ----------------
extern "C" void kernel_launch(void* const* d_in, const int* in_sizes, int n_in,
                              void* d_out, int out_size) {
    const float* x = (const float*)d_in[0];
    const float* w = (const float*)d_in[1];
    float* out = (float*)d_out;

    __half *xh, *xl, *wh, *wl;
    cudaGetSymbolAddress((void**)&xh, g_xh);
    cudaGetSymbolAddress((void**)&xl, g_xl);
    cudaGetSymbolAddress((void**)&wh, g_wh);
    cudaGetSymbolAddress((void**)&wl, g_wl);

    prep16<<<(NPTS * DDIM / 4) / 256, 256>>>(x, xh, xl);
    prep16<<<(KNEU * DDIM / 4) / 256, 256>>>(w, wh, wl);
    w2_kernel<<<KNEU / 8, 256>>>(w);

    cudaFuncSetAttribute(som_mma, cudaFuncAttributeMaxDynamicSharedMemorySize, SMEM_DYN);
    som_mma<<<NPTS / BM, NTH, SMEM_DYN>>>(x, w, out);
}

// round 11
// speedup vs baseline: 3.1331x; 1.0755x over previous
#include <cuda_runtime.h>
#include <cuda_fp16.h>
#include <cstdint>

// KohonenMap: 3xFP16-split mma.sync (hh+hl+lh) top-2 pass + exact fp32 refine.
// R11: BK=32 pipeline stages (halve mbarrier wait overhead; TRYWAIT=90cyc each),
// NST=3, two k16 sub-rounds per stage, 2 CTAs/SM.
#define NPTS 65536
#define KNEU 4096
#define DDIM 512
#define BM 64
#define BN 128
#define NTH 256
#define NST 3
#define NCHUNK (KNEU / BN)    // 32
#define NSTEP  (DDIM / 32)    // 16 BK-32 steps per chunk
#define TOTSTEP (NCHUNK * NSTEP)   // 512
#define MARGIN_TH 0.05f

__device__ __half g_xh[(size_t)NPTS * DDIM];
__device__ __half g_xl[(size_t)NPTS * DDIM];
__device__ __half g_wh[(size_t)KNEU * DDIM];
__device__ __half g_wl[(size_t)KNEU * DDIM];
__device__ float  g_w2[KNEU];

// stage (BK=32, 80B-padded rows; 64B data per row):
//   Ah[64x80] Al[64x80] Bh[128x80] Bl[128x80] = 30720 B
#define SROW 80
#define STG_AH 0
#define STG_AL 5120
#define STG_BH 10240
#define STG_BL 20480
#define STG_BYTES 30720
#define SMEM_DYN (NST * STG_BYTES)   // 92160 -> 2 CTAs/SM

extern __shared__ char dynsmem[];

__device__ __forceinline__ uint32_t smem_u32(const void* p) {
    uint32_t a;
    asm("{ .reg .u64 t; cvta.to.shared.u64 t, %1; cvt.u32.u64 %0, t; }" : "=r"(a) : "l"(p));
    return a;
}
__device__ __forceinline__ void cp16(uint32_t dst, const void* src) {
    asm volatile("cp.async.cg.shared.global [%0], [%1], 16;" :: "r"(dst), "l"(src));
}

#define MBAR_INIT(mb, c) \
    asm volatile("mbarrier.init.shared.b64 [%0], %1;" :: "r"(mb), "r"(c) : "memory")
#define MBAR_ARRIVE(mb) \
    asm volatile("mbarrier.arrive.shared.b64 _, [%0];" :: "r"(mb) : "memory")
#define CPASYNC_MBAR_ARRIVE(mb) \
    asm volatile("cp.async.mbarrier.arrive.noinc.shared.b64 [%0];" :: "r"(mb) : "memory")

#define MBAR_WAIT_PARITY(mbar_addr, par) do {                                            \
    uint32_t _mb = (uint32_t)(mbar_addr); uint32_t _p = (uint32_t)(par); uint32_t _done; \
    asm volatile("{ .reg .pred p; mbarrier.try_wait.parity.acquire.cta.shared::cta.b64 " \
                 "p, [%1], %2; selp.b32 %0,1,0,p; }"                                     \
                 : "=r"(_done) : "r"(_mb), "r"(_p) : "memory");                          \
    if (!_done) {                                                                        \
        asm volatile("{ .reg .pred P1; WL_%=: "                                          \
            "mbarrier.try_wait.parity.acquire.cta.shared::cta.b64 P1, [%0], %1, 0x989680;"\
            " @P1 bra.uni WD_%=; bra.uni WL_%=; WD_%=: }"                                \
            :: "r"(_mb), "r"(_p) : "memory");                                            \
    }                                                                                    \
} while (0)

__device__ __forceinline__ void ldm_x4(uint32_t* r, uint32_t addr) {
    asm volatile("ldmatrix.sync.aligned.m8n8.x4.shared.b16 {%0,%1,%2,%3}, [%4];"
        : "=r"(r[0]), "=r"(r[1]), "=r"(r[2]), "=r"(r[3]) : "r"(addr));
}

__device__ __forceinline__ void mma16816(float* c, const uint32_t* a, const uint32_t* b) {
    asm volatile(
        "mma.sync.aligned.m16n8k16.row.col.f32.f16.f16.f32 "
        "{%0,%1,%2,%3}, {%4,%5,%6,%7}, {%8,%9}, {%0,%1,%2,%3};"
        : "+f"(c[0]), "+f"(c[1]), "+f"(c[2]), "+f"(c[3])
        : "r"(a[0]), "r"(a[1]), "r"(a[2]), "r"(a[3]), "r"(b[0]), "r"(b[1]));
}

__device__ __forceinline__ void top2_upd(float d, int idx, float& v1, int& i1,
                                         float& v2, int& i2) {
    if (d < v1 || (d == v1 && idx < i1)) { v2 = v1; i2 = i1; v1 = d; i1 = idx; }
    else if (d < v2 || (d == v2 && idx < i2)) { v2 = d; i2 = idx; }
}

// ---------------- prep kernels ----------------
__global__ void prep16(const float* __restrict__ s, __half* __restrict__ dh,
                       __half* __restrict__ dl) {
    size_t i = (size_t)blockIdx.x * blockDim.x + threadIdx.x;
    float4 v = reinterpret_cast<const float4*>(s)[i];
    __half hx = __float2half_rn(v.x), hy = __float2half_rn(v.y);
    __half hz = __float2half_rn(v.z), hw = __float2half_rn(v.w);
    __half lx = __float2half_rn(v.x - __half2float(hx));
    __half ly = __float2half_rn(v.y - __half2float(hy));
    __half lz = __float2half_rn(v.z - __half2float(hz));
    __half lw = __float2half_rn(v.w - __half2float(hw));
    __half2 h01 = __halves2half2(hx, hy), h23 = __halves2half2(hz, hw);
    __half2 l01 = __halves2half2(lx, ly), l23 = __halves2half2(lz, lw);
    uint2 ph, pl;
    ph.x = *reinterpret_cast<uint32_t*>(&h01); ph.y = *reinterpret_cast<uint32_t*>(&h23);
    pl.x = *reinterpret_cast<uint32_t*>(&l01); pl.y = *reinterpret_cast<uint32_t*>(&l23);
    reinterpret_cast<uint2*>(dh)[i] = ph;
    reinterpret_cast<uint2*>(dl)[i] = pl;
}

__global__ void w2_kernel(const float* __restrict__ w) {
    int warp = (blockIdx.x * blockDim.x + threadIdx.x) >> 5;
    int lane = threadIdx.x & 31;
    if (warp >= KNEU) return;
    const float4* row = reinterpret_cast<const float4*>(w + (size_t)warp * DDIM);
    float s = 0.f;
#pragma unroll
    for (int i = 0; i < DDIM / 128; ++i) {
        float4 v = row[lane + i * 32];
        s += v.x * v.x + v.y * v.y + v.z * v.z + v.w * v.w;
    }
#pragma unroll
    for (int off = 16; off > 0; off >>= 1) s += __shfl_xor_sync(0xffffffff, s, off);
    if (lane == 0) g_w2[warp] = s;
}

// ---------------- main kernel ----------------
__global__ void __launch_bounds__(NTH, 2)
som_mma(const float* __restrict__ x, const float* __restrict__ w,
        float* __restrict__ out) {
    __shared__ __align__(8) uint64_t mbar[2 * NST];   // full[0..2], empty[3..5]
    __shared__ float s_v1[BM][4], s_v2[BM][4];
    __shared__ int   s_i1[BM][4], s_i2[BM][4];
    __shared__ int   s_bmu[BM];

    const int tid = threadIdx.x;
    const int wid = tid >> 5;
    const int lane = tid & 31;
    const int g4 = lane >> 2;
    const int tig = lane & 3;
    const int warpM = wid & 1;        // 2 M-warps, 32 rows each
    const int warpN = wid >> 1;       // 4 N-warps, 32 cols each
    const int rowBase = blockIdx.x * BM;
    const uint32_t sb = smem_u32(dynsmem);
    const uint32_t mb = smem_u32(mbar);

    // ldmatrix lane decomposition (proven mapping from R7-R10)
    const int lr = lane & 15;
    const int lh = lane >> 4;
    const int bt = lane >> 3;
    const int br = lane & 7;
    const int b_noff = ((bt >> 1) << 3) + br;
    const int b_koff = (bt & 1) << 4;

    // fill mapping: per stage, each thread issues 6 cp16:
    //   B: row bR=tid>>1, quarters bQ,bQ+1 (bQ=(tid&1)*2) for Bh and Bl
    //   A: row aR=tid>>2, quarter aQ=tid&3 for Ah and Al
    const int bR = tid >> 1;
    const int bQ = (tid & 1) * 2;
    const int aR = tid >> 2;
    const int aQ = tid & 3;

    if (tid == 0) {
#pragma unroll
        for (int s = 0; s < NST; ++s) {
            MBAR_INIT(mb + s * 8, NTH);             // full: 256 cp-arrivals
            MBAR_INIT(mb + (NST + s) * 8, 8);       // empty: 8 warp-arrivals
        }
    }
    __syncthreads();   // barriers visible before any arrival

    // prologue: fill stages 0,1 (gn=0,1; chunk 0)
#pragma unroll
    for (int p = 0; p < NST - 1; ++p) {
        const int kk = p * 32;
        const uint32_t stg = sb + p * STG_BYTES;
        cp16(stg + STG_BH + bR * SROW + bQ * 16,
             &g_wh[(size_t)bR * DDIM + kk + bQ * 8]);
        cp16(stg + STG_BH + bR * SROW + (bQ + 1) * 16,
             &g_wh[(size_t)bR * DDIM + kk + (bQ + 1) * 8]);
        cp16(stg + STG_BL + bR * SROW + bQ * 16,
             &g_wl[(size_t)bR * DDIM + kk + bQ * 8]);
        cp16(stg + STG_BL + bR * SROW + (bQ + 1) * 16,
             &g_wl[(size_t)bR * DDIM + kk + (bQ + 1) * 8]);
        cp16(stg + STG_AH + aR * SROW + aQ * 16,
             &g_xh[(size_t)(rowBase + aR) * DDIM + kk + aQ * 8]);
        cp16(stg + STG_AL + aR * SROW + aQ * 16,
             &g_xl[(size_t)(rowBase + aR) * DDIM + kk + aQ * 8]);
        CPASYNC_MBAR_ARRIVE(mb + p * 8);
    }

    // running top-2 per owned sub-row
    float rv1[2][2], rv2[2][2];
    int   ri1[2][2], ri2[2][2];
#pragma unroll
    for (int a = 0; a < 2; ++a)
#pragma unroll
        for (int b = 0; b < 2; ++b) {
            rv1[a][b] = 3.4e38f; rv2[a][b] = 3.4e38f;
            ri1[a][b] = 0x7fffffff; ri2[a][b] = 0x7fffffff;
        }

    // incremental mod-3 stage/phase state
    int cst = 0, cph = 0;         // consumer (stage, phase) for step gs
    int pst = 2, pph = 0;         // producer (stage, phase-of-cycle) for gn = gs+2
    int gn = NST - 1;             // next stage to fill

    for (int ch = 0; ch < NCHUNK; ++ch) {
        float2 w2r[4];
#pragma unroll
        for (int nt = 0; nt < 4; ++nt)
            w2r[nt] = *reinterpret_cast<const float2*>(
                &g_w2[ch * BN + warpN * 32 + nt * 8 + tig * 2]);

        float acc[2][4][4];
#pragma unroll
        for (int mt = 0; mt < 2; ++mt)
#pragma unroll
            for (int nt = 0; nt < 4; ++nt)
#pragma unroll
                for (int i = 0; i < 4; ++i) acc[mt][nt][i] = 0.f;

        for (int s = 0; s < NSTEP; ++s) {
            // ---- consumer: wait stage full ----
            MBAR_WAIT_PARITY(mb + cst * 8, cph);
            const uint32_t stg32 = sb + cst * STG_BYTES;

            // two k16 sub-rounds over this BK=32 stage
#pragma unroll
            for (int sub = 0; sub < 2; ++sub) {
                const int so = sub * 32;
                uint32_t ah[2][4], al[2][4], bh[4][2], bl[4][2];

                uint32_t aaddr = stg32 + STG_AH + (warpM * 32 + lr) * SROW + lh * 16 + so;
                ldm_x4(ah[0], aaddr);
                ldm_x4(ah[1], aaddr + 16 * SROW);
                uint32_t aladdr = stg32 + STG_AL + (warpM * 32 + lr) * SROW + lh * 16 + so;
                ldm_x4(al[0], aladdr);
                ldm_x4(al[1], aladdr + 16 * SROW);
                uint32_t bhaddr = stg32 + STG_BH + (warpN * 32 + b_noff) * SROW + b_koff + so;
                ldm_x4(&bh[0][0], bhaddr);
                ldm_x4(&bh[2][0], bhaddr + 16 * SROW);
                uint32_t bladdr = stg32 + STG_BL + (warpN * 32 + b_noff) * SROW + b_koff + so;
                ldm_x4(&bl[0][0], bladdr);
                ldm_x4(&bl[2][0], bladdr + 16 * SROW);

#pragma unroll
                for (int mt = 0; mt < 2; ++mt)
#pragma unroll
                    for (int nt = 0; nt < 4; ++nt)
                        mma16816(acc[mt][nt], ah[mt], bh[nt]);   // hi*hi
#pragma unroll
                for (int mt = 0; mt < 2; ++mt)
#pragma unroll
                    for (int nt = 0; nt < 4; ++nt)
                        mma16816(acc[mt][nt], ah[mt], bl[nt]);   // hi*lo
#pragma unroll
                for (int mt = 0; mt < 2; ++mt)
#pragma unroll
                    for (int nt = 0; nt < 4; ++nt)
                        mma16816(acc[mt][nt], al[mt], bh[nt]);   // lo*hi
            }

            // warp done with this stage
            if (lane == 0) MBAR_ARRIVE(mb + (NST + cst) * 8);
            if (++cst == NST) { cst = 0; cph ^= 1; }

            // ---- producer: fill stage for gn ----
            if (gn < TOTSTEP) {
                if (gn >= NST)   // wait consumers of previous cycle
                    MBAR_WAIT_PARITY(mb + (NST + pst) * 8, pph ^ 1);
                const int nc = (gn >> 4) * BN;
                const int kk = (gn & 15) * 32;
                const uint32_t stg = sb + pst * STG_BYTES;
                cp16(stg + STG_BH + bR * SROW + bQ * 16,
                     &g_wh[(size_t)(nc + bR) * DDIM + kk + bQ * 8]);
                cp16(stg + STG_BH + bR * SROW + (bQ + 1) * 16,
                     &g_wh[(size_t)(nc + bR) * DDIM + kk + (bQ + 1) * 8]);
                cp16(stg + STG_BL + bR * SROW + bQ * 16,
                     &g_wl[(size_t)(nc + bR) * DDIM + kk + bQ * 8]);
                cp16(stg + STG_BL + bR * SROW + (bQ + 1) * 16,
                     &g_wl[(size_t)(nc + bR) * DDIM + kk + (bQ + 1) * 8]);
                cp16(stg + STG_AH + aR * SROW + aQ * 16,
                     &g_xh[(size_t)(rowBase + aR) * DDIM + kk + aQ * 8]);
                cp16(stg + STG_AL + aR * SROW + aQ * 16,
                     &g_xl[(size_t)(rowBase + aR) * DDIM + kk + aQ * 8]);
                CPASYNC_MBAR_ARRIVE(mb + pst * 8);
                ++gn;
                if (++pst == NST) { pst = 0; pph ^= 1; }
            }
        }

        // epilogue: per-chunk local top-2, butterfly over 4 threads, merge
#pragma unroll
        for (int mt = 0; mt < 2; ++mt) {
#pragma unroll
            for (int r2 = 0; r2 < 2; ++r2) {
                float lv1 = 3.4e38f, lv2 = 3.4e38f;
                int li1 = 0x7fffffff, li2 = 0x7fffffff;
#pragma unroll
                for (int nt = 0; nt < 4; ++nt) {
#pragma unroll
                    for (int c2 = 0; c2 < 2; ++c2) {
                        float dot = acc[mt][nt][r2 * 2 + c2];
                        float w2v = c2 ? w2r[nt].y : w2r[nt].x;
                        float dist = fmaf(-2.f, dot, w2v);
                        int idx = ch * BN + warpN * 32 + nt * 8 + tig * 2 + c2;
                        top2_upd(dist, idx, lv1, li1, lv2, li2);
                    }
                }
#pragma unroll
                for (int off = 1; off < 4; off <<= 1) {
                    float o1 = __shfl_xor_sync(0xffffffffu, lv1, off);
                    int   p1 = __shfl_xor_sync(0xffffffffu, li1, off);
                    float o2 = __shfl_xor_sync(0xffffffffu, lv2, off);
                    int   p2 = __shfl_xor_sync(0xffffffffu, li2, off);
                    top2_upd(o1, p1, lv1, li1, lv2, li2);
                    top2_upd(o2, p2, lv1, li1, lv2, li2);
                }
                top2_upd(lv1, li1, rv1[mt][r2], ri1[mt][r2], rv2[mt][r2], ri2[mt][r2]);
                top2_upd(lv2, li2, rv1[mt][r2], ri1[mt][r2], rv2[mt][r2], ri2[mt][r2]);
            }
        }
    }

    // cross-warp merge + margin test + exact refine
    if (tig == 0) {
#pragma unroll
        for (int mt = 0; mt < 2; ++mt)
#pragma unroll
            for (int r2 = 0; r2 < 2; ++r2) {
                int row = warpM * 32 + mt * 16 + g4 + r2 * 8;
                s_v1[row][warpN] = rv1[mt][r2]; s_i1[row][warpN] = ri1[mt][r2];
                s_v2[row][warpN] = rv2[mt][r2]; s_i2[row][warpN] = ri2[mt][r2];
            }
    }
    __syncthreads();
    if (tid < BM) {
        float v1 = s_v1[tid][0], v2 = s_v2[tid][0];
        int   i1 = s_i1[tid][0], i2 = s_i2[tid][0];
#pragma unroll
        for (int wn = 1; wn < 4; ++wn) {
            top2_upd(s_v1[tid][wn], s_i1[tid][wn], v1, i1, v2, i2);
            top2_upd(s_v2[tid][wn], s_i2[tid][wn], v1, i1, v2, i2);
        }
        int bmu = i1;
        if (v2 - v1 < MARGIN_TH) {
            // exact fp32 refine: identical FMA chain to the validated r1 kernel
            const float* xr = x + (size_t)(rowBase + tid) * DDIM;
            const float* w1p = w + (size_t)i1 * DDIM;
            const float* w2p = w + (size_t)i2 * DDIM;
            float a1 = 0.f, a2 = 0.f;
#pragma unroll 8
            for (int k = 0; k < DDIM; ++k) {
                float xv = xr[k];
                a1 = fmaf(xv, w1p[k], a1);
                a2 = fmaf(xv, w2p[k], a2);
            }
            float d1 = fmaf(-2.f, a1, g_w2[i1]);
            float d2 = fmaf(-2.f, a2, g_w2[i2]);
            if (d2 < d1 || (d2 == d1 && i2 < i1)) bmu = i2;
        }
        s_bmu[tid] = bmu;
    }
    __syncthreads();

    for (int t = tid; t < BM * (DDIM / 4); t += NTH) {
        int r = t >> 7;
        int cc = t & 127;
        reinterpret_cast<float4*>(out + (size_t)(rowBase + r) * DDIM)[cc] =
            reinterpret_cast<const float4*>(w + (size_t)s_bmu[r] * DDIM)[cc];
    }
}

// ---------------- launch ----------------
extern "C" void kernel_launch(void* const* d_in, const int* in_sizes, int n_in,
                              void* d_out, int out_size) {
    const float* x = (const float*)d_in[0];
    const float* w = (const float*)d_in[1];
    float* out = (float*)d_out;

    __half *xh, *xl, *wh, *wl;
    cudaGetSymbolAddress((void**)&xh, g_xh);
    cudaGetSymbolAddress((void**)&xl, g_xl);
    cudaGetSymbolAddress((void**)&wh, g_wh);
    cudaGetSymbolAddress((void**)&wl, g_wl);

    prep16<<<(NPTS * DDIM / 4) / 256, 256>>>(x, xh, xl);
    prep16<<<(KNEU * DDIM / 4) / 256, 256>>>(w, wh, wl);
    w2_kernel<<<KNEU / 8, 256>>>(w);

    cudaFuncSetAttribute(som_mma, cudaFuncAttributeMaxDynamicSharedMemorySize, SMEM_DYN);
    som_mma<<<NPTS / BM, NTH, SMEM_DYN>>>(x, w, out);
}